// round 1
// baseline (speedup 1.0000x reference)
#include <cuda_runtime.h>
#include <cstdint>

#define THREADS 256
#define EPT 7          // elements per thread
#define NMODE 256
#define RCORE 8

// Shared memory layout (floats):
//   mid[0]: 16384  (64KB)  double-buffered middle-core slab
//   mid[1]: 16384  (64KB)
//   g0s   : 2048   (8KB)   G0, layout [idx][r]
//   g7s   : 2048   (8KB)   G7 transposed, layout [idx][r]
// total 36864 floats = 147456 bytes
#define SMEM_BYTES 147456

// Stage one middle core (8 x 256 x 8 floats = 16384 floats = 4096 float4)
// Global layout  : float4 index g = r*512 + u,  u = idx*2 + half
// Shared layout  : float4 index s = idx*16 + half*8 + r  (slice = 256B contiguous,
//                  bank-group of a chunk = r  -> deterministic spread)
// Mapping: lane provides r = lane>>2 (8 groups x 4 lanes -> conflict-free STS),
//          4 consecutive lanes read 64B contiguous global (sector-dense).
__device__ __forceinline__ void stage_mid(float* dst, const float* __restrict__ src, int tid)
{
    const int lane = tid & 31;
    const int wrp  = tid >> 5;
    const int r    = lane >> 2;
    const int m    = lane & 3;
    const char* gbase = (const char*)src;
    unsigned sbase = (unsigned)__cvta_generic_to_shared(dst);
#pragma unroll
    for (int t = 0; t < 16; t++) {
        int u = wrp * 64 + t * 4 + m;
        long goff = ((long)(r * 512 + u)) << 4;                    // bytes
        unsigned soff = (unsigned)((((u >> 1) << 4) + ((u & 1) << 3) + r) << 4); // bytes
        asm volatile("cp.async.cg.shared.global [%0], [%1], 16;\n"
                     :: "r"(sbase + soff), "l"(gbase + goff) : "memory");
    }
    asm volatile("cp.async.commit_group;\n" ::: "memory");
}

__global__ void __launch_bounds__(THREADS, 1)
tt_gather_kernel(const float* __restrict__ G0, const float* __restrict__ G1,
                 const float* __restrict__ G2, const float* __restrict__ G3,
                 const float* __restrict__ G4, const float* __restrict__ G5,
                 const float* __restrict__ G6, const float* __restrict__ G7,
                 const int* __restrict__ states, const int* __restrict__ actions,
                 float* __restrict__ out, int Btot)
{
    extern __shared__ float smem[];
    float* mid0 = smem;
    float* mid1 = smem + 16384;
    float* g0s  = smem + 32768;
    float* g7s  = smem + 34816;

    const int tid = threadIdx.x;
    const int rho = tid & 7;

    // Kick off async staging of G1 into mid0 immediately.
    stage_mid(mid0, G1, tid);

    // Stage G0 (already [idx][r] in global: 1 x 256 x 8) — plain float4 copy.
    {
        const float4* s = (const float4*)G0;
        float4* d = (float4*)g0s;
        d[2 * tid]     = s[2 * tid];
        d[2 * tid + 1] = s[2 * tid + 1];
    }
    // Stage G7 transposed: global [r][idx] (8 x 256 x 1) -> smem [idx][r].
#pragma unroll
    for (int r = 0; r < 8; r++)
        g7s[tid * 8 + r] = G7[r * 256 + tid];

    // Per-thread rotated row order (constant for whole kernel).
    int ridx[8];
#pragma unroll
    for (int c = 0; c < 8; c++) ridx[c] = (c + rho) & 7;

    // Load all indices for my EPT elements, convert to offsets.
    const int base = blockIdx.x * (THREADS * EPT) + tid;
    unsigned actmask = 0;
    int g0off[EPT], g7off[EPT], soff[EPT][6];
#pragma unroll
    for (int i = 0; i < EPT; i++) {
        int e = base + i * THREADS;
        bool act = (e < Btot);
        int ec = act ? e : 0;
        if (act) actmask |= (1u << i);
        const int* sp = states + ec * 7;
        g0off[i] = sp[0];
#pragma unroll
        for (int k = 0; k < 6; k++) soff[i][k] = sp[k + 1] << 8;   // byte offset: idx*256
        g7off[i] = actions[ec];
    }

    asm volatile("cp.async.wait_group 0;\n" ::: "memory");
    __syncthreads();

    // Init rotated vec from G0: w[j] = vec0[(j+rho)&7]
    float w[EPT][8];
#pragma unroll
    for (int i = 0; i < EPT; i++) {
        const float* p0 = g0s + g0off[i] * 8;
#pragma unroll
        for (int j = 0; j < 8; j++) w[i][j] = p0[ridx[j]];
    }

    const float* nextG[6] = { G1, G2, G3, G4, G5, G6 };  // nextG[k] = core (k+1)

#pragma unroll
    for (int k = 1; k <= 6; k++) {
        const float* cur = (k & 1) ? mid0 : mid1;
        if (k < 6) stage_mid((k & 1) ? mid1 : mid0, nextG[k], tid);

#pragma unroll
        for (int i = 0; i < EPT; i++) {
            const char* p = (const char*)cur + soff[i][k - 1];
            float nv[8];
#pragma unroll
            for (int s = 0; s < 8; s++) nv[s] = 0.f;
#pragma unroll
            for (int c = 0; c < 8; c++) {
                // chunk (r = ridx[c], half): lanes hit all 8 bank-groups, 4 lanes each
                const float4 glo = *(const float4*)(p + (ridx[c] << 4));
                const float4 ghi = *(const float4*)(p + 128 + (ridx[c] << 4));
                const float wc = w[i][c];
                nv[0] = fmaf(wc, glo.x, nv[0]);
                nv[1] = fmaf(wc, glo.y, nv[1]);
                nv[2] = fmaf(wc, glo.z, nv[2]);
                nv[3] = fmaf(wc, glo.w, nv[3]);
                nv[4] = fmaf(wc, ghi.x, nv[4]);
                nv[5] = fmaf(wc, ghi.y, nv[5]);
                nv[6] = fmaf(wc, ghi.z, nv[6]);
                nv[7] = fmaf(wc, ghi.w, nv[7]);
            }
            // Barrel-rotate nv left by rho into w[i] (predicated selects, no branches).
            const bool r1 = (rho & 1) != 0, r2 = (rho & 2) != 0, r4 = (rho & 4) != 0;
            float a[8], b[8];
#pragma unroll
            for (int j = 0; j < 8; j++) a[j] = r1 ? nv[(j + 1) & 7] : nv[j];
#pragma unroll
            for (int j = 0; j < 8; j++) b[j] = r2 ? a[(j + 2) & 7] : a[j];
#pragma unroll
            for (int j = 0; j < 8; j++) w[i][j] = r4 ? b[(j + 4) & 7] : b[j];
        }

        if (k < 6) {
            asm volatile("cp.async.wait_group 0;\n" ::: "memory");
            __syncthreads();
        }
    }

    // Final: dot with G7 slice and store.
#pragma unroll
    for (int i = 0; i < EPT; i++) {
        const float* p7 = g7s + g7off[i] * 8;
        float acc = 0.f;
#pragma unroll
        for (int c = 0; c < 8; c++) acc = fmaf(w[i][c], p7[ridx[c]], acc);
        if (actmask & (1u << i)) out[base + i * THREADS] = acc;
    }
}

extern "C" void kernel_launch(void* const* d_in, const int* in_sizes, int n_in,
                              void* d_out, int out_size)
{
    const float* G0 = (const float*)d_in[0];
    const float* G1 = (const float*)d_in[1];
    const float* G2 = (const float*)d_in[2];
    const float* G3 = (const float*)d_in[3];
    const float* G4 = (const float*)d_in[4];
    const float* G5 = (const float*)d_in[5];
    const float* G6 = (const float*)d_in[6];
    const float* G7 = (const float*)d_in[7];
    const int* states  = (const int*)d_in[8];
    const int* actions = (const int*)d_in[9];
    const int B = in_sizes[9];   // actions element count

    cudaFuncSetAttribute(tt_gather_kernel,
                         cudaFuncAttributeMaxDynamicSharedMemorySize, SMEM_BYTES);

    const int per_block = THREADS * EPT;
    const int grid = (B + per_block - 1) / per_block;
    tt_gather_kernel<<<grid, THREADS, SMEM_BYTES>>>(
        G0, G1, G2, G3, G4, G5, G6, G7, states, actions, (float*)d_out, B);
}